// round 16
// baseline (speedup 1.0000x reference)
#include <cuda_runtime.h>
#include <cstdint>

// Problem constants (from reference setup_inputs)
#define B_  8
#define N_  131072            // 2^17
#define M_  (B_ * N_)         // 1048576 points
#define C_  76
#define PTS 128               // points per decode block

// radix sort tiles: 4096 items; scatter blocks 512thr x 8 items
#define STILE 4096
#define SNT   (M_ / STILE)    // 256 tiles per pass
#define STH   512             // scatter threads (16 warps)
#define SIT   8               // items per scatter thread
#define WSEG  (32 * SIT)      // 256 contiguous items per warp
#define HTH   256             // hist/count threads
#define HIT   16              // items per hist/count thread

// rank+gather tiling
#define GTH    256
#define GIT    8
#define GTILE  (GTH * GIT)    // 2048
#define NTILES (M_ / GTILE)   // 512
#define GSEG   (32 * GIT)     // 256 contiguous items per warp

#define FLAG_AGG (1u << 30)
#define FLAG_INC (2u << 30)
#define VALMASK  ((1u << 30) - 1u)
#define LBW      16

#define FULLM 0xffffffffu

// ---------------- device scratch (no allocation allowed) ----------------
struct State {                                   // zeroed once per launch (~21 KB)
    unsigned int counters[8];                    // [0..3] barriers, [6] rg
    unsigned int hist[4][256];                   // global per-pass histograms
    unsigned int rg_status[NTILES][8];           // rank_gather lookback
};
__device__ State        g_state;
__device__ unsigned int g_bin_excl[4][256];      // overwritten each launch
__device__ unsigned int g_tp[256][SNT];          // per-digit tile counts -> prefixes
__device__ float        g_props[(size_t)M_ * 8]; // 32 MB
__device__ uint2        g_pairs[M_];             // 8 MB (key, val)
__device__ uint2        g_pairs_alt[M_];         // 8 MB

// L2-coherent load — for reads after an in-kernel grid barrier
__device__ __forceinline__ unsigned int ldcg(const unsigned int* p)
{
    unsigned int v;
    asm volatile("ld.global.cg.u32 %0, [%1];" : "=r"(v) : "l"(p));
    return v;
}

// ---------------- decode: thread per point, smem-staged ----------------
__global__ __launch_bounds__(PTS) void decode_kernel(
    const float* __restrict__ scores,
    const float* __restrict__ reg,
    const float* __restrict__ xyz,
    const float* __restrict__ anchor)
{
    __shared__ float s[PTS * 77];
    __shared__ float sxyz[PTS * 3];

    const int tid  = threadIdx.x;
    const int base = blockIdx.x * PTS;

    const float* gsrc = reg + (size_t)base * C_;
    #pragma unroll
    for (int k = 0; k < C_; ++k) {
        const int i = tid + k * PTS;
        const int p = i / C_;
        const int c = i - p * C_;
        s[p * 77 + c] = gsrc[i];
    }
    #pragma unroll
    for (int k = 0; k < 3; ++k)
        sxyz[tid + k * PTS] = xyz[(size_t)base * 3 + tid + k * PTS];
    __syncthreads();

    const int    p = base + tid;
    const float* r = s + tid * 77;

    int xb = 0; float xv = r[0];
    #pragma unroll
    for (int j = 1; j < 12; ++j) { float v = r[j];      if (v > xv) { xv = v; xb = j; } }
    int zb = 0; float zv = r[12];
    #pragma unroll
    for (int j = 1; j < 12; ++j) { float v = r[12 + j]; if (v > zv) { zv = v; zb = j; } }
    int rb = 0; float rv = r[49];
    #pragma unroll
    for (int j = 1; j < 12; ++j) { float v = r[49 + j]; if (v > rv) { rv = v; rb = j; } }

    const float x_res  = r[24 + xb];
    const float z_res  = r[36 + zb];
    const float y_off  = r[48];
    const float ry_res = r[61 + rb];
    const float hr = r[73], wr = r[74], lr = r[75];

    const float roi0 = sxyz[tid * 3 + 0];
    const float roi1 = sxyz[tid * 3 + 1];
    const float roi2 = sxyz[tid * 3 + 2];

    const float an0 = __ldg(anchor);
    const float an1 = __ldg(anchor + 1);
    const float an2 = __ldg(anchor + 2);

    const float LOC_BIN = 0.5f, HALF = 0.25f, SCOPE = 3.0f;
    const float pos_x = (float)xb * LOC_BIN + HALF - SCOPE + x_res * LOC_BIN;
    const float pos_z = (float)zb * LOC_BIN + HALF - SCOPE + z_res * LOC_BIN;
    const float pos_y = roi1 + y_off;

    const float TWO_PI = 6.28318530717958647692f;
    const float PI_    = 3.14159265358979323846f;
    const float APC    = 0.52359877559829887308f;   // 2*pi/12
    float ry = (float)rb * APC + ry_res * (APC * 0.5f);
    ry = fmodf(ry, TWO_PI);
    if (ry < 0.f) ry += TWO_PI;
    if (ry > PI_) ry -= TWO_PI;

    const float h_ = hr * an0 + an0;
    const float w_ = wr * an1 + an1;
    const float l_ = lr * an2 + an2;

    const float px = pos_x + roi0;
    const float pz = pos_z + roi2;
    const float py = pos_y + h_ * 0.5f;

    const float sc = __ldg(scores + p);

    float4* pp = (float4*)g_props;
    pp[2 * (size_t)p]     = make_float4(px, py, pz, h_);
    pp[2 * (size_t)p + 1] = make_float4(w_, l_, ry, sc);

    unsigned int u = __float_as_uint(sc);
    u ^= (u & 0x80000000u) ? 0xFFFFFFFFu : 0x80000000u;
    g_pairs[p] = make_uint2(~u, (unsigned int)p);   // (sortable key, index)
}

// shuffle-based exclusive scan; NW warps (NW<=32), one value per thread
template<int NW>
__device__ __forceinline__ unsigned int block_excl_scan(
    unsigned int x, unsigned int* s_warp, int lane, int warp)
{
    unsigned int v = x;
    #pragma unroll
    for (int d = 1; d < 32; d <<= 1) {
        unsigned int n = __shfl_up_sync(FULLM, v, d);
        if (lane >= d) v += n;
    }
    if (lane == 31) s_warp[warp] = v;
    __syncthreads();
    if (warp == 0) {
        unsigned int w = (lane < NW) ? s_warp[lane] : 0u;
        #pragma unroll
        for (int d = 1; d < NW; d <<= 1) {
            unsigned int n = __shfl_up_sync(FULLM, w, d);
            if (lane >= d) w += n;
        }
        if (lane < NW) s_warp[lane] = w;
    }
    __syncthreads();
    const unsigned int base = (warp > 0) ? s_warp[warp - 1] : 0u;
    return base + v - x;
}

// single-wave grid barrier (SNT=256 blocks; co-residency via minBlocksPerSM)
__device__ __forceinline__ void grid_barrier(unsigned int* ctr)
{
    __threadfence();
    __syncthreads();
    if (threadIdx.x == 0) {
        atomicAdd(ctr, 1u);
        while (*(volatile unsigned int*)ctr < SNT) { }
    }
    __syncthreads();
}

// ---- fused: global hists + pass-0 tile counts -> barrier -> prefixes ----
__global__ __launch_bounds__(HTH, 2) void hist_prefix_kernel(const uint2* __restrict__ pairs)
{
    __shared__ unsigned int h[4][256];
    __shared__ unsigned int s_warp[8];
    const int tid = threadIdx.x, lane = tid & 31, warp = tid >> 5;
    #pragma unroll
    for (int p = 0; p < 4; ++p) h[p][tid] = 0;
    __syncthreads();
    const size_t base = (size_t)blockIdx.x * STILE;
    unsigned int key[HIT];
    #pragma unroll
    for (int k = 0; k < HIT; ++k)                     // batched loads (MLP)
        key[k] = pairs[base + k * HTH + tid].x;
    #pragma unroll
    for (int k = 0; k < HIT; ++k) {
        atomicAdd(&h[0][key[k] & 255u], 1u);
        atomicAdd(&h[1][(key[k] >> 8) & 255u], 1u);
        atomicAdd(&h[2][(key[k] >> 16) & 255u], 1u);
        atomicAdd(&h[3][key[k] >> 24], 1u);
    }
    __syncthreads();
    #pragma unroll
    for (int p = 0; p < 4; ++p) atomicAdd(&g_state.hist[p][tid], h[p][tid]);
    g_tp[tid][blockIdx.x] = h[0][tid];               // pass-0 tile counts

    grid_barrier(&g_state.counters[7]);

    // prefix for digit d over 256 tiles (cross-barrier reads: L2-coherent)
    const int d = blockIdx.x;
    const unsigned int x = ldcg(&g_tp[d][tid]);
    g_tp[d][tid] = block_excl_scan<8>(x, s_warp, lane, warp);
    if (d < 4) {
        __syncthreads();
        const unsigned int hx = ldcg(&g_state.hist[d][tid]);
        g_bin_excl[d][tid] = block_excl_scan<8>(hx, s_warp, lane, warp);
    }
}

// ---- fused: pass-k tile counts -> barrier -> prefixes (passes 1..3) ----
template<int SHIFT, int PASS>
__global__ __launch_bounds__(HTH, 2) void count_prefix_kernel(const uint2* __restrict__ pairs)
{
    __shared__ unsigned int h[256];
    __shared__ unsigned int s_warp[8];
    const int tid = threadIdx.x, lane = tid & 31, warp = tid >> 5;
    h[tid] = 0;
    __syncthreads();
    const size_t base = (size_t)blockIdx.x * STILE;
    unsigned int key[HIT];
    #pragma unroll
    for (int k = 0; k < HIT; ++k)                     // batched loads (MLP)
        key[k] = pairs[base + k * HTH + tid].x;
    #pragma unroll
    for (int k = 0; k < HIT; ++k)
        atomicAdd(&h[(key[k] >> SHIFT) & 255u], 1u);
    __syncthreads();
    g_tp[tid][blockIdx.x] = h[tid];

    grid_barrier(&g_state.counters[PASS]);

    const int d = blockIdx.x;
    const unsigned int x = ldcg(&g_tp[d][tid]);
    g_tp[d][tid] = block_excl_scan<8>(x, s_warp, lane, warp);
}

// ------- scatter pass: packed (key,val) uint2, smem-staged, coalesced ------
template<int SHIFT, int PASS>
__global__ __launch_bounds__(STH, 2) void scatter_pass(
    const uint2* __restrict__ pairs_in,
    uint2* __restrict__ pairs_out)
{
    __shared__ uint2        s_pairs[STILE];      // 32 KB
    __shared__ unsigned int s_wc[16][256];       // 16 KB
    __shared__ unsigned int s_tile_excl[256];
    __shared__ unsigned int s_gbase[256];
    __shared__ unsigned int s_warp[16];

    const int tid = threadIdx.x, lane = tid & 31, warp = tid >> 5;
    const unsigned lt = (1u << lane) - 1u;

    const int    tile  = blockIdx.x;
    const size_t wbase = (size_t)tile * STILE + (size_t)warp * WSEG;

    // batched pair preload (MLP=8, single LDG.64 per item) while zeroing
    uint2 pr[SIT];
    #pragma unroll
    for (int k = 0; k < SIT; ++k)
        pr[k] = pairs_in[wbase + k * 32 + lane];
    #pragma unroll
    for (int i = 0; i < 8; ++i) (&s_wc[0][0])[tid + i * STH] = 0;
    __syncthreads();

    unsigned short rnk[SIT];
    unsigned int* wc = s_wc[warp];

    // warp-private stable ranking (8 slices, keys in registers)
    #pragma unroll
    for (int k = 0; k < SIT; ++k) {
        const unsigned int d     = (pr[k].x >> SHIFT) & 255u;
        const unsigned int peers = __match_any_sync(FULLM, d);
        const unsigned int cnt   = wc[d];
        rnk[k] = (unsigned short)(cnt + __popc(peers & lt));
        if ((peers >> lane) == 1u)
            wc[d] = cnt + __popc(peers);
        __syncwarp();
    }
    __syncthreads();

    // digit-owner (tid<256) cross-warp exclusive scan over 16 warps
    unsigned int agg = 0;
    if (tid < 256) {
        unsigned int run = 0;
        #pragma unroll
        for (int w = 0; w < 16; ++w) {
            const unsigned int c = s_wc[w][tid];
            s_wc[w][tid] = run;
            run += c;
        }
        agg = run;
    }
    // intra-tile digit base + precomputed global base
    const unsigned int texcl = block_excl_scan<16>(agg, s_warp, lane, warp);
    if (tid < 256) {
        s_tile_excl[tid] = texcl;
        s_gbase[tid] = g_bin_excl[PASS][tid] + g_tp[tid][tile] - texcl;
    }
    __syncthreads();

    // stage into smem grouped by digit (one ST.64 per item)
    #pragma unroll
    for (int k = 0; k < SIT; ++k) {
        const unsigned int d   = (pr[k].x >> SHIFT) & 255u;
        const unsigned int pos = s_tile_excl[d] + s_wc[warp][d] + rnk[k];
        s_pairs[pos] = pr[k];
    }
    __syncthreads();

    // coalesced global scatter (one LD.64 + ST.64 per item)
    #pragma unroll
    for (int k = 0; k < SIT; ++k) {
        const int j = k * STH + tid;
        const uint2 p2 = s_pairs[j];
        const unsigned int d  = (p2.x >> SHIFT) & 255u;
        pairs_out[s_gbase[d] + j] = p2;
    }
}

// windowed decoupled lookback (rank_gather only; 8-bin state)
__device__ __forceinline__ unsigned int lookback_windowed(
    volatile unsigned int* col, size_t stride, int tile)
{
    unsigned int excl = 0;
    int t = tile - 1;
    bool done = false;
    while (!done) {
        unsigned int w[LBW];
        #pragma unroll
        for (int i = 0; i < LBW; ++i) {
            const int tt = t - i;
            w[i] = (tt >= 0) ? col[(size_t)tt * stride] : (FLAG_INC | 0u);
        }
        #pragma unroll
        for (int i = 0; i < LBW; ++i) {
            const int tt = t - i;
            if (tt >= 0) while (w[i] == 0u) w[i] = col[(size_t)tt * stride];
        }
        #pragma unroll
        for (int i = 0; i < LBW; ++i) {
            if (!done) {
                excl += w[i] & VALMASK;
                if (w[i] & FLAG_INC) done = true;
            }
        }
        t -= LBW;
    }
    return excl;
}

// ------- fused stable 8-way rank (windowed lookback) + gather/scatter -------
__global__ __launch_bounds__(GTH) void rank_gather_kernel(
    const uint2* __restrict__ sorted_pairs,
    float4* __restrict__ out)
{
    __shared__ unsigned int s_wc[8][8];
    __shared__ unsigned int s_excl[8];
    __shared__ unsigned int s_tile;

    const int tid  = threadIdx.x;
    const int lane = tid & 31;
    const int warp = tid >> 5;
    const unsigned lt = (1u << lane) - 1u;

    if (tid == 0) s_tile = atomicAdd(&g_state.counters[6], 1u);
    if (tid < 64) (&s_wc[0][0])[tid] = 0;
    __syncthreads();
    const int    tile  = (int)s_tile;
    const size_t wbase = (size_t)tile * GTILE + (size_t)warp * GSEG;

    unsigned int v[GIT]; unsigned int row[GIT]; unsigned short rnk[GIT];
    unsigned int* wc = s_wc[warp];

    #pragma unroll
    for (int k = 0; k < GIT; ++k)                     // batched loads (MLP)
        v[k] = __ldg(&sorted_pairs[wbase + k * 32 + lane].y);

    #pragma unroll
    for (int k = 0; k < GIT; ++k) {
        row[k] = v[k] >> 17;
        const unsigned int peers = __match_any_sync(FULLM, row[k]);
        const unsigned int cnt   = wc[row[k]];
        rnk[k] = (unsigned short)(cnt + __popc(peers & lt));
        if ((peers >> lane) == 1u)
            wc[row[k]] = cnt + __popc(peers);
        __syncwarp();
    }
    __syncthreads();

    if (tid < 8) {
        unsigned int run = 0;
        #pragma unroll
        for (int w = 0; w < 8; ++w) {
            const unsigned int c = s_wc[w][tid];
            s_wc[w][tid] = run;
            run += c;
        }
        const unsigned int agg = run;
        if (tile == 0) {
            ((volatile unsigned int*)g_state.rg_status[0])[tid] = FLAG_INC | agg;
            __threadfence();
            s_excl[tid] = 0;
        } else {
            ((volatile unsigned int*)g_state.rg_status[tile])[tid] = FLAG_AGG | agg;
            __threadfence();
            const unsigned int excl = lookback_windowed(&g_state.rg_status[0][tid], 8, tile);
            ((volatile unsigned int*)g_state.rg_status[tile])[tid] = FLAG_INC | (excl + agg);
            __threadfence();
            s_excl[tid] = excl;
        }
    }
    __syncthreads();

    const float4* pp = (const float4*)g_props;
    #pragma unroll
    for (int k = 0; k < GIT; ++k) {
        const unsigned int src = v[k];
        const unsigned int dst = row[k] * N_ + s_excl[row[k]] + s_wc[warp][row[k]] + rnk[k];
        out[2 * (size_t)dst]     = __ldg(&pp[2 * (size_t)src]);
        out[2 * (size_t)dst + 1] = __ldg(&pp[2 * (size_t)src + 1]);
    }
}

// ---------------- launch ----------------
extern "C" void kernel_launch(void* const* d_in, const int* in_sizes, int n_in,
                              void* d_out, int out_size)
{
    const float* scores = (const float*)d_in[0];
    const float* reg    = (const float*)d_in[1];
    const float* xyz    = (const float*)d_in[2];
    const float* anchor = (const float*)d_in[3];

    void* pst; cudaGetSymbolAddress(&pst, g_state);
    cudaMemsetAsync(pst, 0, sizeof(State));

    decode_kernel<<<M_ / PTS, PTS>>>(scores, reg, xyz, anchor);

    void *p0, *p1;
    cudaGetSymbolAddress(&p0, g_pairs);
    cudaGetSymbolAddress(&p1, g_pairs_alt);

    const uint2* P0 = (const uint2*)p0;
    const uint2* P1 = (const uint2*)p1;

    hist_prefix_kernel<<<SNT, HTH>>>(P0);          // hists + barrier + prefixes
    scatter_pass< 0, 0><<<SNT, STH>>>(P0, (uint2*)p1);

    count_prefix_kernel< 8, 1><<<SNT, HTH>>>(P1);
    scatter_pass< 8, 1><<<SNT, STH>>>(P1, (uint2*)p0);

    count_prefix_kernel<16, 2><<<SNT, HTH>>>(P0);
    scatter_pass<16, 2><<<SNT, STH>>>(P0, (uint2*)p1);

    count_prefix_kernel<24, 3><<<SNT, HTH>>>(P1);
    scatter_pass<24, 3><<<SNT, STH>>>(P1, (uint2*)p0);

    rank_gather_kernel<<<NTILES, GTH>>>(P0, (float4*)d_out);
}

// round 17
// speedup vs baseline: 1.0136x; 1.0136x over previous
#include <cuda_runtime.h>
#include <cstdint>

// Problem constants (from reference setup_inputs)
#define B_  8
#define N_  131072            // 2^17
#define M_  (B_ * N_)         // 1048576 points
#define C_  76
#define PTS 128               // points per decode block

// radix sort tiles: 4096 items; scatter blocks 512thr x 8 items
#define STILE 4096
#define SNT   (M_ / STILE)    // 256 tiles per pass
#define STH   512             // scatter threads (16 warps)
#define SIT   8               // items per scatter thread
#define WSEG  (32 * SIT)      // 256 contiguous items per warp
#define HTH   256             // hist/count threads
#define HIT   16              // items per hist/count thread

// rank+gather tiling
#define GTH    256
#define GIT    8
#define GTILE  (GTH * GIT)    // 2048
#define NTILES (M_ / GTILE)   // 512
#define GSEG   (32 * GIT)     // 256 contiguous items per warp

#define FLAG_AGG (1u << 30)
#define FLAG_INC (2u << 30)
#define VALMASK  ((1u << 30) - 1u)
#define LBW      16

#define FULLM 0xffffffffu

// ---------------- device scratch (no allocation allowed) ----------------
struct State {                                   // zeroed once per launch (~21 KB)
    unsigned int counters[8];                    // [0..3] barriers, [6] rg, [7] hist
    unsigned int hist[4][256];                   // global per-pass histograms
    unsigned int rg_status[NTILES][8];           // rank_gather lookback
};
__device__ State        g_state;
__device__ unsigned int g_bin_excl[4][256];      // overwritten each launch
__device__ unsigned int g_tp[256][SNT];          // per-digit tile counts -> prefixes
__device__ float        g_props[(size_t)M_ * 8]; // 32 MB
__device__ unsigned int g_keys[M_];
__device__ unsigned int g_keys_alt[M_];
__device__ unsigned int g_vals[M_];
__device__ unsigned int g_vals_alt[M_];

// L2-coherent load — for reads after an in-kernel grid barrier
__device__ __forceinline__ unsigned int ldcg(const unsigned int* p)
{
    unsigned int v;
    asm volatile("ld.global.cg.u32 %0, [%1];" : "=r"(v) : "l"(p));
    return v;
}

// ---------------- keygen: scores -> sortable keys + indices (tiny) --------
__global__ __launch_bounds__(256) void keygen_kernel(const float* __restrict__ scores)
{
    const int p = blockIdx.x * 256 + threadIdx.x;
    const float sc = __ldg(scores + p);
    unsigned int u = __float_as_uint(sc);
    u ^= (u & 0x80000000u) ? 0xFFFFFFFFu : 0x80000000u;
    g_keys[p] = ~u;              // ascending == descending score
    g_vals[p] = (unsigned int)p;
}

// ---------------- props decode: thread per point, smem-staged -------------
// Runs CONCURRENTLY with the sort on a second stream (only rank_gather needs it).
__global__ __launch_bounds__(PTS) void props_kernel(
    const float* __restrict__ scores,
    const float* __restrict__ reg,
    const float* __restrict__ xyz,
    const float* __restrict__ anchor)
{
    __shared__ float s[PTS * 77];
    __shared__ float sxyz[PTS * 3];

    const int tid  = threadIdx.x;
    const int base = blockIdx.x * PTS;

    const float* gsrc = reg + (size_t)base * C_;
    #pragma unroll
    for (int k = 0; k < C_; ++k) {
        const int i = tid + k * PTS;
        const int p = i / C_;
        const int c = i - p * C_;
        s[p * 77 + c] = gsrc[i];
    }
    #pragma unroll
    for (int k = 0; k < 3; ++k)
        sxyz[tid + k * PTS] = xyz[(size_t)base * 3 + tid + k * PTS];
    __syncthreads();

    const int    p = base + tid;
    const float* r = s + tid * 77;

    int xb = 0; float xv = r[0];
    #pragma unroll
    for (int j = 1; j < 12; ++j) { float v = r[j];      if (v > xv) { xv = v; xb = j; } }
    int zb = 0; float zv = r[12];
    #pragma unroll
    for (int j = 1; j < 12; ++j) { float v = r[12 + j]; if (v > zv) { zv = v; zb = j; } }
    int rb = 0; float rv = r[49];
    #pragma unroll
    for (int j = 1; j < 12; ++j) { float v = r[49 + j]; if (v > rv) { rv = v; rb = j; } }

    const float x_res  = r[24 + xb];
    const float z_res  = r[36 + zb];
    const float y_off  = r[48];
    const float ry_res = r[61 + rb];
    const float hr = r[73], wr = r[74], lr = r[75];

    const float roi0 = sxyz[tid * 3 + 0];
    const float roi1 = sxyz[tid * 3 + 1];
    const float roi2 = sxyz[tid * 3 + 2];

    const float an0 = __ldg(anchor);
    const float an1 = __ldg(anchor + 1);
    const float an2 = __ldg(anchor + 2);

    const float LOC_BIN = 0.5f, HALF = 0.25f, SCOPE = 3.0f;
    const float pos_x = (float)xb * LOC_BIN + HALF - SCOPE + x_res * LOC_BIN;
    const float pos_z = (float)zb * LOC_BIN + HALF - SCOPE + z_res * LOC_BIN;
    const float pos_y = roi1 + y_off;

    const float TWO_PI = 6.28318530717958647692f;
    const float PI_    = 3.14159265358979323846f;
    const float APC    = 0.52359877559829887308f;   // 2*pi/12
    float ry = (float)rb * APC + ry_res * (APC * 0.5f);
    ry = fmodf(ry, TWO_PI);
    if (ry < 0.f) ry += TWO_PI;
    if (ry > PI_) ry -= TWO_PI;

    const float h_ = hr * an0 + an0;
    const float w_ = wr * an1 + an1;
    const float l_ = lr * an2 + an2;

    const float px = pos_x + roi0;
    const float pz = pos_z + roi2;
    const float py = pos_y + h_ * 0.5f;

    const float sc = __ldg(scores + p);

    float4* pp = (float4*)g_props;
    pp[2 * (size_t)p]     = make_float4(px, py, pz, h_);
    pp[2 * (size_t)p + 1] = make_float4(w_, l_, ry, sc);
}

// shuffle-based exclusive scan; NW warps (NW<=32), one value per thread
template<int NW>
__device__ __forceinline__ unsigned int block_excl_scan(
    unsigned int x, unsigned int* s_warp, int lane, int warp)
{
    unsigned int v = x;
    #pragma unroll
    for (int d = 1; d < 32; d <<= 1) {
        unsigned int n = __shfl_up_sync(FULLM, v, d);
        if (lane >= d) v += n;
    }
    if (lane == 31) s_warp[warp] = v;
    __syncthreads();
    if (warp == 0) {
        unsigned int w = (lane < NW) ? s_warp[lane] : 0u;
        #pragma unroll
        for (int d = 1; d < NW; d <<= 1) {
            unsigned int n = __shfl_up_sync(FULLM, w, d);
            if (lane >= d) w += n;
        }
        if (lane < NW) s_warp[lane] = w;
    }
    __syncthreads();
    const unsigned int base = (warp > 0) ? s_warp[warp - 1] : 0u;
    return base + v - x;
}

// single-wave grid barrier (SNT=256 blocks; co-residency via minBlocksPerSM)
__device__ __forceinline__ void grid_barrier(unsigned int* ctr)
{
    __threadfence();
    __syncthreads();
    if (threadIdx.x == 0) {
        atomicAdd(ctr, 1u);
        while (*(volatile unsigned int*)ctr < SNT) { }
    }
    __syncthreads();
}

// ---- fused: global hists + pass-0 tile counts -> barrier -> prefixes ----
__global__ __launch_bounds__(HTH, 2) void hist_prefix_kernel(const unsigned int* __restrict__ keys)
{
    __shared__ unsigned int h[4][256];
    __shared__ unsigned int s_warp[8];
    const int tid = threadIdx.x, lane = tid & 31, warp = tid >> 5;
    #pragma unroll
    for (int p = 0; p < 4; ++p) h[p][tid] = 0;
    __syncthreads();
    const size_t base = (size_t)blockIdx.x * STILE;
    unsigned int key[HIT];
    #pragma unroll
    for (int k = 0; k < HIT; ++k)                     // batched loads (MLP)
        key[k] = keys[base + k * HTH + tid];
    #pragma unroll
    for (int k = 0; k < HIT; ++k) {
        atomicAdd(&h[0][key[k] & 255u], 1u);
        atomicAdd(&h[1][(key[k] >> 8) & 255u], 1u);
        atomicAdd(&h[2][(key[k] >> 16) & 255u], 1u);
        atomicAdd(&h[3][key[k] >> 24], 1u);
    }
    __syncthreads();
    #pragma unroll
    for (int p = 0; p < 4; ++p) atomicAdd(&g_state.hist[p][tid], h[p][tid]);
    g_tp[tid][blockIdx.x] = h[0][tid];               // pass-0 tile counts

    grid_barrier(&g_state.counters[7]);

    // prefix for digit d over 256 tiles (cross-barrier reads: L2-coherent)
    const int d = blockIdx.x;
    const unsigned int x = ldcg(&g_tp[d][tid]);
    g_tp[d][tid] = block_excl_scan<8>(x, s_warp, lane, warp);
    if (d < 4) {
        __syncthreads();
        const unsigned int hx = ldcg(&g_state.hist[d][tid]);
        g_bin_excl[d][tid] = block_excl_scan<8>(hx, s_warp, lane, warp);
    }
}

// ---- fused: pass-k tile counts -> barrier -> prefixes (passes 1..3) ----
template<int SHIFT, int PASS>
__global__ __launch_bounds__(HTH, 2) void count_prefix_kernel(const unsigned int* __restrict__ keys)
{
    __shared__ unsigned int h[256];
    __shared__ unsigned int s_warp[8];
    const int tid = threadIdx.x, lane = tid & 31, warp = tid >> 5;
    h[tid] = 0;
    __syncthreads();
    const size_t base = (size_t)blockIdx.x * STILE;
    unsigned int key[HIT];
    #pragma unroll
    for (int k = 0; k < HIT; ++k)                     // batched loads (MLP)
        key[k] = keys[base + k * HTH + tid];
    #pragma unroll
    for (int k = 0; k < HIT; ++k)
        atomicAdd(&h[(key[k] >> SHIFT) & 255u], 1u);
    __syncthreads();
    g_tp[tid][blockIdx.x] = h[tid];

    grid_barrier(&g_state.counters[PASS]);

    const int d = blockIdx.x;
    const unsigned int x = ldcg(&g_tp[d][tid]);
    g_tp[d][tid] = block_excl_scan<8>(x, s_warp, lane, warp);
}

// ------- scatter pass: 512-thread blocks (16 warps x 8 items), smem-staged --
template<int SHIFT, int PASS, bool WRITE_KEYS>
__global__ __launch_bounds__(STH, 2) void scatter_pass(
    const unsigned int* __restrict__ keys_in,
    const unsigned int* __restrict__ vals_in,
    unsigned int* __restrict__ keys_out,
    unsigned int* __restrict__ vals_out)
{
    __shared__ unsigned int s_keys[STILE];       // 16 KB
    __shared__ unsigned int s_vals[STILE];       // 16 KB
    __shared__ unsigned int s_wc[16][256];       // 16 KB
    __shared__ unsigned int s_tile_excl[256];
    __shared__ unsigned int s_gbase[256];
    __shared__ unsigned int s_warp[16];

    const int tid = threadIdx.x, lane = tid & 31, warp = tid >> 5;
    const unsigned lt = (1u << lane) - 1u;

    const int    tile  = blockIdx.x;
    const size_t wbase = (size_t)tile * STILE + (size_t)warp * WSEG;

    // batched key+val preload (MLP) while zeroing counters
    unsigned int key[SIT], val[SIT];
    #pragma unroll
    for (int k = 0; k < SIT; ++k) {
        key[k] = keys_in[wbase + k * 32 + lane];
        val[k] = vals_in[wbase + k * 32 + lane];
    }
    #pragma unroll
    for (int i = 0; i < 8; ++i) (&s_wc[0][0])[tid + i * STH] = 0;
    __syncthreads();

    unsigned short rnk[SIT];
    unsigned int* wc = s_wc[warp];

    // warp-private stable ranking (keys in registers, 8 slices)
    #pragma unroll
    for (int k = 0; k < SIT; ++k) {
        const unsigned int d     = (key[k] >> SHIFT) & 255u;
        const unsigned int peers = __match_any_sync(FULLM, d);
        const unsigned int cnt   = wc[d];
        rnk[k] = (unsigned short)(cnt + __popc(peers & lt));
        if ((peers >> lane) == 1u)
            wc[d] = cnt + __popc(peers);
        __syncwarp();
    }
    __syncthreads();

    // digit-owner (tid<256) cross-warp exclusive scan over 16 warps
    unsigned int agg = 0;
    if (tid < 256) {
        unsigned int run = 0;
        #pragma unroll
        for (int w = 0; w < 16; ++w) {
            const unsigned int c = s_wc[w][tid];
            s_wc[w][tid] = run;
            run += c;
        }
        agg = run;
    }
    // intra-tile digit base + precomputed global base
    const unsigned int texcl = block_excl_scan<16>(agg, s_warp, lane, warp);
    if (tid < 256) {
        s_tile_excl[tid] = texcl;
        s_gbase[tid] = g_bin_excl[PASS][tid] + g_tp[tid][tile] - texcl;
    }
    __syncthreads();

    // stage into smem grouped by digit
    #pragma unroll
    for (int k = 0; k < SIT; ++k) {
        const unsigned int d   = (key[k] >> SHIFT) & 255u;
        const unsigned int pos = s_tile_excl[d] + s_wc[warp][d] + rnk[k];
        s_keys[pos] = key[k];
        s_vals[pos] = val[k];
    }
    __syncthreads();

    // coalesced global scatter
    #pragma unroll
    for (int k = 0; k < SIT; ++k) {
        const int j = k * STH + tid;
        const unsigned int kk = s_keys[j];
        const unsigned int d  = (kk >> SHIFT) & 255u;
        const unsigned int dest = s_gbase[d] + j;
        if (WRITE_KEYS) keys_out[dest] = kk;
        vals_out[dest] = s_vals[j];
    }
}

// windowed decoupled lookback (rank_gather only; 8-bin state)
__device__ __forceinline__ unsigned int lookback_windowed(
    volatile unsigned int* col, size_t stride, int tile)
{
    unsigned int excl = 0;
    int t = tile - 1;
    bool done = false;
    while (!done) {
        unsigned int w[LBW];
        #pragma unroll
        for (int i = 0; i < LBW; ++i) {
            const int tt = t - i;
            w[i] = (tt >= 0) ? col[(size_t)tt * stride] : (FLAG_INC | 0u);
        }
        #pragma unroll
        for (int i = 0; i < LBW; ++i) {
            const int tt = t - i;
            if (tt >= 0) while (w[i] == 0u) w[i] = col[(size_t)tt * stride];
        }
        #pragma unroll
        for (int i = 0; i < LBW; ++i) {
            if (!done) {
                excl += w[i] & VALMASK;
                if (w[i] & FLAG_INC) done = true;
            }
        }
        t -= LBW;
    }
    return excl;
}

// ------- fused stable 8-way rank (windowed lookback) + gather/scatter -------
__global__ __launch_bounds__(GTH) void rank_gather_kernel(
    const unsigned int* __restrict__ sorted_vals,
    float4* __restrict__ out)
{
    __shared__ unsigned int s_wc[8][8];
    __shared__ unsigned int s_excl[8];
    __shared__ unsigned int s_tile;

    const int tid  = threadIdx.x;
    const int lane = tid & 31;
    const int warp = tid >> 5;
    const unsigned lt = (1u << lane) - 1u;

    if (tid == 0) s_tile = atomicAdd(&g_state.counters[6], 1u);
    if (tid < 64) (&s_wc[0][0])[tid] = 0;
    __syncthreads();
    const int    tile  = (int)s_tile;
    const size_t wbase = (size_t)tile * GTILE + (size_t)warp * GSEG;

    unsigned int v[GIT]; unsigned int row[GIT]; unsigned short rnk[GIT];
    unsigned int* wc = s_wc[warp];

    #pragma unroll
    for (int k = 0; k < GIT; ++k)                     // batched loads (MLP)
        v[k] = __ldg(sorted_vals + wbase + k * 32 + lane);

    #pragma unroll
    for (int k = 0; k < GIT; ++k) {
        row[k] = v[k] >> 17;
        const unsigned int peers = __match_any_sync(FULLM, row[k]);
        const unsigned int cnt   = wc[row[k]];
        rnk[k] = (unsigned short)(cnt + __popc(peers & lt));
        if ((peers >> lane) == 1u)
            wc[row[k]] = cnt + __popc(peers);
        __syncwarp();
    }
    __syncthreads();

    if (tid < 8) {
        unsigned int run = 0;
        #pragma unroll
        for (int w = 0; w < 8; ++w) {
            const unsigned int c = s_wc[w][tid];
            s_wc[w][tid] = run;
            run += c;
        }
        const unsigned int agg = run;
        if (tile == 0) {
            ((volatile unsigned int*)g_state.rg_status[0])[tid] = FLAG_INC | agg;
            __threadfence();
            s_excl[tid] = 0;
        } else {
            ((volatile unsigned int*)g_state.rg_status[tile])[tid] = FLAG_AGG | agg;
            __threadfence();
            const unsigned int excl = lookback_windowed(&g_state.rg_status[0][tid], 8, tile);
            ((volatile unsigned int*)g_state.rg_status[tile])[tid] = FLAG_INC | (excl + agg);
            __threadfence();
            s_excl[tid] = excl;
        }
    }
    __syncthreads();

    const float4* pp = (const float4*)g_props;
    #pragma unroll
    for (int k = 0; k < GIT; ++k) {
        const unsigned int src = v[k];
        const unsigned int dst = row[k] * N_ + s_excl[row[k]] + s_wc[warp][row[k]] + rnk[k];
        out[2 * (size_t)dst]     = __ldg(&pp[2 * (size_t)src]);
        out[2 * (size_t)dst + 1] = __ldg(&pp[2 * (size_t)src + 1]);
    }
}

// ---------------- launch: dual-stream overlap (props decode || sort) -------
extern "C" void kernel_launch(void* const* d_in, const int* in_sizes, int n_in,
                              void* d_out, int out_size)
{
    const float* scores = (const float*)d_in[0];
    const float* reg    = (const float*)d_in[1];
    const float* xyz    = (const float*)d_in[2];
    const float* anchor = (const float*)d_in[3];

    // Streams/events created ONCE on the first (uncaptured) correctness call;
    // reused inside graph capture (fork/join pattern is capture-legal).
    static cudaStream_t s2 = nullptr;
    static cudaEvent_t  evFork = nullptr, evJoin = nullptr;
    if (s2 == nullptr) {
        cudaStreamCreateWithFlags(&s2, cudaStreamNonBlocking);
        cudaEventCreateWithFlags(&evFork, cudaEventDisableTiming);
        cudaEventCreateWithFlags(&evJoin, cudaEventDisableTiming);
    }

    void* pst; cudaGetSymbolAddress(&pst, g_state);
    cudaMemsetAsync(pst, 0, sizeof(State));

    // fork: props decode runs concurrently with the entire sort chain
    cudaEventRecord(evFork, 0);
    cudaStreamWaitEvent(s2, evFork, 0);
    props_kernel<<<M_ / PTS, PTS, 0, s2>>>(scores, reg, xyz, anchor);
    cudaEventRecord(evJoin, s2);

    void *pk, *pka, *pv, *pva;
    cudaGetSymbolAddress(&pk,  g_keys);
    cudaGetSymbolAddress(&pka, g_keys_alt);
    cudaGetSymbolAddress(&pv,  g_vals);
    cudaGetSymbolAddress(&pva, g_vals_alt);

    const unsigned int* K0 = (const unsigned int*)pk;
    const unsigned int* V0 = (const unsigned int*)pv;
    unsigned int* K1 = (unsigned int*)pka;
    unsigned int* V1 = (unsigned int*)pva;

    keygen_kernel<<<M_ / 256, 256>>>(scores);

    hist_prefix_kernel<<<SNT, HTH>>>(K0);          // hists + barrier + prefixes
    scatter_pass< 0, 0, true ><<<SNT, STH>>>(K0, V0, K1, V1);

    count_prefix_kernel< 8, 1><<<SNT, HTH>>>(K1);
    scatter_pass< 8, 1, true ><<<SNT, STH>>>(K1, V1, (unsigned int*)pk, (unsigned int*)pv);

    count_prefix_kernel<16, 2><<<SNT, HTH>>>(K0);
    scatter_pass<16, 2, true ><<<SNT, STH>>>(K0, V0, K1, V1);

    count_prefix_kernel<24, 3><<<SNT, HTH>>>(K1);
    scatter_pass<24, 3, false><<<SNT, STH>>>(K1, V1, (unsigned int*)pk, (unsigned int*)pv);

    // join: rank_gather needs props
    cudaStreamWaitEvent(0, evJoin, 0);
    rank_gather_kernel<<<NTILES, GTH>>>(V0, (float4*)d_out);
}